// round 5
// baseline (speedup 1.0000x reference)
#include <cuda_runtime.h>
#include <float.h>

#define NB   8
#define NSEQ 1024
#define NDIM 1024
#define NH   16
#define ND   64
#define MTOT (NB*NSEQ)      // 8192
#define ATTN_SCALE 0.03125f // DIM^-0.5 = 1/32

// Scratch (device globals: allocation-free per harness rules)
__device__ float g_Q [NB*NH*NSEQ*ND];   // [B,H,N,D]
__device__ float g_K [NB*NH*NSEQ*ND];
__device__ float g_V [NB*NH*NSEQ*ND];
__device__ float g_AO[NB*NSEQ*NDIM];    // attention out, [B,N,DIM]
__device__ int   g_mask[NB*NSEQ];       // canonical padded mask, 1 = visible

// ---------------------------------------------------------------------------
// Mask decode: auto-detect element width of the raw bool mask buffer
// (harness may widen numpy bool to int32/float32/bf16/uint8), write padded
// [B, N] int mask with position 0 forced visible (CLS).
// For 4-byte elems, (word != 0) == (value != 0), so i32/f32 confusion is
// harmless; we only need the element SIZE.
// ---------------------------------------------------------------------------
__global__ void decode_mask_kernel(const unsigned char* __restrict__ raw)
{
    const unsigned int* w = (const unsigned int*)raw;
    bool w4 = true, w2 = true;
    #pragma unroll
    for (int i = 0; i < 32; i++) {
        unsigned int v = w[i];
        if (v != 0u && v != 1u && v != 0x3F800000u) w4 = false;
        if (v != 0u && v != 0x3F803F80u && v != 0x3F800000u &&
            v != 0x00003F80u && v != 0x00010001u && v != 0x00000001u &&
            v != 0x00010000u) w2 = false;
    }
    int e = blockIdx.x * blockDim.x + threadIdx.x;
    if (e >= NB * NSEQ) return;
    int b = e / NSEQ, n = e % NSEQ;
    int val;
    if (n == 0) {
        val = 1;
    } else {
        int idx = b * (NSEQ - 1) + (n - 1);
        if (w4)      val = (((const unsigned int*)raw)[idx]   != 0u);
        else if (w2) val = (((const unsigned short*)raw)[idx] != 0);
        else         val = (raw[idx] != 0);
    }
    g_mask[e] = val;
}

// ---------------------------------------------------------------------------
// GEMM1: C[8192,3072] = X[8192,1024] @ [Wqk;Wv]^T ; epilogue adds pos to Q,K
// and scatters into [B,H,N,D].
// ---------------------------------------------------------------------------
__global__ __launch_bounds__(256) void qkv_gemm(
    const float* __restrict__ X, const float* __restrict__ Wqk,
    const float* __restrict__ Wv, const float* __restrict__ pos)
{
    __shared__ float As[16][128];
    __shared__ float Bs[16][128];
    const int K_ = NDIM;
    const int tid = threadIdx.x;
    const int tx = tid & 15, ty = tid >> 4;
    const int m0 = blockIdx.y * 128;
    const int n0 = blockIdx.x * 128;
    const float* Bbase = (n0 < 2048) ? (Wqk + (size_t)n0 * K_)
                                     : (Wv  + (size_t)(n0 - 2048) * K_);

    float acc[8][8];
    #pragma unroll
    for (int i = 0; i < 8; i++)
        #pragma unroll
        for (int j = 0; j < 8; j++) acc[i][j] = 0.f;

    for (int k0 = 0; k0 < K_; k0 += 16) {
        #pragma unroll
        for (int it = 0; it < 2; it++) {
            int v   = tid + it * 256;     // 0..511
            int row = v >> 2;             // 0..127
            int c4  = (v & 3) * 4;        // 0,4,8,12
            float4 a = *(const float4*)(X + (size_t)(m0 + row) * K_ + k0 + c4);
            As[c4+0][row] = a.x; As[c4+1][row] = a.y;
            As[c4+2][row] = a.z; As[c4+3][row] = a.w;
            float4 b = *(const float4*)(Bbase + (size_t)row * K_ + k0 + c4);
            Bs[c4+0][row] = b.x; Bs[c4+1][row] = b.y;
            Bs[c4+2][row] = b.z; Bs[c4+3][row] = b.w;
        }
        __syncthreads();
        #pragma unroll
        for (int kk = 0; kk < 16; kk++) {
            float a[8], b[8];
            #pragma unroll
            for (int i = 0; i < 8; i++) a[i] = As[kk][ty*8 + i];
            #pragma unroll
            for (int j = 0; j < 8; j++) b[j] = Bs[kk][tx*8 + j];
            #pragma unroll
            for (int i = 0; i < 8; i++)
                #pragma unroll
                for (int j = 0; j < 8; j++) acc[i][j] += a[i] * b[j];
        }
        __syncthreads();
    }

    // Epilogue: scatter to Q/K/V [B,H,N,D]; add pos for Q and K.
    #pragma unroll
    for (int i = 0; i < 8; i++) {
        int m = m0 + ty*8 + i;
        int b = m >> 10, n = m & 1023;
        #pragma unroll
        for (int j = 0; j < 8; j++) {
            int jg = n0 + tx*8 + j;
            float c = acc[i][j];
            if (jg < 2048) {
                int jj = jg & 1023;
                c += pos[(size_t)m * NDIM + jj];
                int h = jj >> 6, d = jj & 63;
                float* dst = (jg < 1024) ? g_Q : g_K;
                dst[(size_t)(b*NH + h) * (NSEQ*ND) + n*ND + d] = c;
            } else {
                int jj = jg - 2048;
                int h = jj >> 6, d = jj & 63;
                g_V[(size_t)(b*NH + h) * (NSEQ*ND) + n*ND + d] = c;
            }
        }
    }
}

// ---------------------------------------------------------------------------
// Flash attention: one CTA per (b,h, 64-row Q tile). Online softmax.
// Masked entries use -FLT_MAX (matches reference: fully masked rows become
// uniform attention).
// ---------------------------------------------------------------------------
#define SSTR 65
#define ATTN_SMEM (3 * 64 * SSTR * 4)

__global__ __launch_bounds__(256) void attn_kernel()
{
    extern __shared__ float sm[];
    float* Qs  = sm;                 // [64][SSTR]
    float* KPs = sm + 64*SSTR;       // K tile, reused as P tile
    float* Vs  = sm + 2*64*SSTR;
    __shared__ int kmask_s[64];

    const int bh = blockIdx.y;
    const int b  = bh >> 4;
    const int h  = bh & 15;
    const int q0 = blockIdx.x * 64;
    const int tid = threadIdx.x;
    const int tx = tid & 15, ty = tid >> 4;
    const int r0 = ty * 4, c0 = tx * 4;

    const float* Qp = g_Q + (size_t)bh * (NSEQ*ND);
    const float* Kp = g_K + (size_t)bh * (NSEQ*ND);
    const float* Vp = g_V + (size_t)bh * (NSEQ*ND);

    // Load Q tile (64x64): 1024 float4, 4 per thread
    #pragma unroll
    for (int it = 0; it < 4; it++) {
        int v   = tid + it * 256;
        int row = v >> 4;
        int c4  = (v & 15) * 4;
        float4 q = *(const float4*)(Qp + (size_t)(q0 + row) * ND + c4);
        Qs[row*SSTR + c4+0] = q.x; Qs[row*SSTR + c4+1] = q.y;
        Qs[row*SSTR + c4+2] = q.z; Qs[row*SSTR + c4+3] = q.w;
    }

    bool rmask[4];
    #pragma unroll
    for (int i = 0; i < 4; i++) {
        int iq = q0 + r0 + i;
        rmask[i] = (g_mask[b*NSEQ + iq] != 0);
    }

    float mrun[4], lrun[4], O[4][4];
    #pragma unroll
    for (int i = 0; i < 4; i++) {
        mrun[i] = -FLT_MAX; lrun[i] = 0.f;
        #pragma unroll
        for (int j = 0; j < 4; j++) O[i][j] = 0.f;
    }

    for (int kt = 0; kt < NSEQ/64; kt++) {
        __syncthreads();  // prev PV done (KPs reuse) + Q ready on first iter
        #pragma unroll
        for (int it = 0; it < 4; it++) {
            int v   = tid + it * 256;
            int row = v >> 4;
            int c4  = (v & 15) * 4;
            const float* ks = Kp + (size_t)(kt*64 + row) * ND + c4;
            float4 kv = *(const float4*)ks;
            KPs[row*SSTR + c4+0] = kv.x; KPs[row*SSTR + c4+1] = kv.y;
            KPs[row*SSTR + c4+2] = kv.z; KPs[row*SSTR + c4+3] = kv.w;
            float4 vv = *(const float4*)(Vp + (size_t)(kt*64 + row) * ND + c4);
            Vs[row*SSTR + c4+0] = vv.x; Vs[row*SSTR + c4+1] = vv.y;
            Vs[row*SSTR + c4+2] = vv.z; Vs[row*SSTR + c4+3] = vv.w;
        }
        if (tid < 64) {
            kmask_s[tid] = g_mask[b*NSEQ + kt*64 + tid];
        }
        __syncthreads();

        // S = Q K^T (4x4 microtile)
        float s[4][4];
        #pragma unroll
        for (int i = 0; i < 4; i++)
            #pragma unroll
            for (int j = 0; j < 4; j++) s[i][j] = 0.f;
        #pragma unroll 8
        for (int k = 0; k < 64; k++) {
            float qa[4], kb[4];
            #pragma unroll
            for (int i = 0; i < 4; i++) qa[i] = Qs[(r0+i)*SSTR + k];
            #pragma unroll
            for (int j = 0; j < 4; j++) kb[j] = KPs[(c0+j)*SSTR + k];
            #pragma unroll
            for (int i = 0; i < 4; i++)
                #pragma unroll
                for (int j = 0; j < 4; j++) s[i][j] += qa[i] * kb[j];
        }

        // scale + mask
        int km[4];
        #pragma unroll
        for (int j = 0; j < 4; j++) km[j] = kmask_s[c0 + j];
        #pragma unroll
        for (int i = 0; i < 4; i++)
            #pragma unroll
            for (int j = 0; j < 4; j++)
                s[i][j] = (rmask[i] && km[j]) ? s[i][j] * ATTN_SCALE : -FLT_MAX;

        // row max across the 16-lane halfwarp
        float tmax[4];
        #pragma unroll
        for (int i = 0; i < 4; i++) {
            tmax[i] = fmaxf(fmaxf(s[i][0], s[i][1]), fmaxf(s[i][2], s[i][3]));
        }
        #pragma unroll
        for (int off = 8; off >= 1; off >>= 1)
            #pragma unroll
            for (int i = 0; i < 4; i++)
                tmax[i] = fmaxf(tmax[i], __shfl_xor_sync(0xffffffffu, tmax[i], off));

        float mnew[4], alpha[4], p[4][4], lsum[4];
        #pragma unroll
        for (int i = 0; i < 4; i++) {
            mnew[i]  = fmaxf(mrun[i], tmax[i]);
            alpha[i] = __expf(mrun[i] - mnew[i]);
            lsum[i]  = 0.f;
            #pragma unroll
            for (int j = 0; j < 4; j++) {
                p[i][j] = __expf(s[i][j] - mnew[i]);
                lsum[i] += p[i][j];
            }
        }
        #pragma unroll
        for (int off = 8; off >= 1; off >>= 1)
            #pragma unroll
            for (int i = 0; i < 4; i++)
                lsum[i] += __shfl_xor_sync(0xffffffffu, lsum[i], off);
        #pragma unroll
        for (int i = 0; i < 4; i++) {
            lrun[i] = lrun[i] * alpha[i] + lsum[i];
            mrun[i] = mnew[i];
            #pragma unroll
            for (int j = 0; j < 4; j++) O[i][j] *= alpha[i];
        }

        __syncthreads();  // all K reads done before overwriting KPs with P
        #pragma unroll
        for (int i = 0; i < 4; i++)
            #pragma unroll
            for (int j = 0; j < 4; j++)
                KPs[(r0+i)*SSTR + (c0+j)] = p[i][j];
        __syncthreads();

        // O += P @ V
        #pragma unroll 8
        for (int k = 0; k < 64; k++) {
            float pa[4], vb[4];
            #pragma unroll
            for (int i = 0; i < 4; i++) pa[i] = KPs[(r0+i)*SSTR + k];
            #pragma unroll
            for (int j = 0; j < 4; j++) vb[j] = Vs[k*SSTR + c0 + j];
            #pragma unroll
            for (int i = 0; i < 4; i++)
                #pragma unroll
                for (int j = 0; j < 4; j++) O[i][j] += pa[i] * vb[j];
        }
    }

    // normalize & store to [B,N,DIM]
    #pragma unroll
    for (int i = 0; i < 4; i++) {
        float inv = 1.0f / lrun[i];
        int iq = q0 + r0 + i;
        float4 o4 = make_float4(O[i][0]*inv, O[i][1]*inv, O[i][2]*inv, O[i][3]*inv);
        *(float4*)(g_AO + (size_t)(b*NSEQ + iq) * NDIM + h*ND + c0) = o4;
    }
}

// ---------------------------------------------------------------------------
// GEMM3: out[8192,1024] = AO @ Wout^T + bout
// ---------------------------------------------------------------------------
__global__ __launch_bounds__(256) void out_gemm(
    const float* __restrict__ Wout, const float* __restrict__ bout,
    float* __restrict__ out)
{
    __shared__ float As[16][128];
    __shared__ float Bs[16][128];
    const int K_ = NDIM;
    const int tid = threadIdx.x;
    const int tx = tid & 15, ty = tid >> 4;
    const int m0 = blockIdx.y * 128;
    const int n0 = blockIdx.x * 128;

    float acc[8][8];
    #pragma unroll
    for (int i = 0; i < 8; i++)
        #pragma unroll
        for (int j = 0; j < 8; j++) acc[i][j] = 0.f;

    for (int k0 = 0; k0 < K_; k0 += 16) {
        #pragma unroll
        for (int it = 0; it < 2; it++) {
            int v   = tid + it * 256;
            int row = v >> 2;
            int c4  = (v & 3) * 4;
            float4 a = *(const float4*)(g_AO + (size_t)(m0 + row) * K_ + k0 + c4);
            As[c4+0][row] = a.x; As[c4+1][row] = a.y;
            As[c4+2][row] = a.z; As[c4+3][row] = a.w;
            float4 b = *(const float4*)(Wout + (size_t)(n0 + row) * K_ + k0 + c4);
            Bs[c4+0][row] = b.x; Bs[c4+1][row] = b.y;
            Bs[c4+2][row] = b.z; Bs[c4+3][row] = b.w;
        }
        __syncthreads();
        #pragma unroll
        for (int kk = 0; kk < 16; kk++) {
            float a[8], b[8];
            #pragma unroll
            for (int i = 0; i < 8; i++) a[i] = As[kk][ty*8 + i];
            #pragma unroll
            for (int j = 0; j < 8; j++) b[j] = Bs[kk][tx*8 + j];
            #pragma unroll
            for (int i = 0; i < 8; i++)
                #pragma unroll
                for (int j = 0; j < 8; j++) acc[i][j] += a[i] * b[j];
        }
        __syncthreads();
    }

    #pragma unroll
    for (int i = 0; i < 8; i++) {
        int m = m0 + ty*8 + i;
        #pragma unroll
        for (int j = 0; j < 8; j++) {
            int jg = n0 + tx*8 + j;
            out[(size_t)m * NDIM + jg] = acc[i][j] + bout[jg];
        }
    }
}

// ---------------------------------------------------------------------------
extern "C" void kernel_launch(void* const* d_in, const int* in_sizes, int n_in,
                              void* d_out, int out_size)
{
    const float*         x    = (const float*)d_in[0];
    const unsigned char* mask = (const unsigned char*)d_in[1];
    const float*         pos  = (const float*)d_in[2];
    const float*         Wqk  = (const float*)d_in[3];
    const float*         Wv   = (const float*)d_in[4];
    const float*         Wout = (const float*)d_in[5];
    const float*         bout = (const float*)d_in[6];
    float*               out  = (float*)d_out;

    cudaFuncSetAttribute(attn_kernel,
                         cudaFuncAttributeMaxDynamicSharedMemorySize, ATTN_SMEM);

    decode_mask_kernel<<<(NB*NSEQ + 255) / 256, 256>>>(mask);
    qkv_gemm<<<dim3(3072/128, MTOT/128), 256>>>(x, Wqk, Wv, pos);
    attn_kernel<<<dim3(NSEQ/64, NB*NH), 256, ATTN_SMEM>>>();
    out_gemm<<<dim3(NDIM/128, MTOT/128), 256>>>(Wout, bout, out);
}